// round 15
// baseline (speedup 1.0000x reference)
#include <cuda_runtime.h>
#include <cuda_fp16.h>
#include <cstdint>

// ColBERT MaxSim on GB300 (sm_103): R13 main (pipelined ldmatrix) + MLP-8 cvt.
// qs: (64, 32, 128) fp32 ; ps: (64, 1024, 128) fp32 ; out: (64, 64) fp32

#define NQ       64
#define TQ       32
#define ND       64
#define TS       1024
#define DIM      128
#define G_Q      4                    // queries per CTA (1 per warp)
#define THREADS  128
#define SN       64                   // doc tokens per chunk
#define NCHUNK   (TS / SN)            // 16
#define ROWB     256                  // bytes per token row in smem (128 f16)
#define BUFB     (SN * ROWB)          // 16 KB per buffer

// fp16 ps scratch (device-global; allocation-free per harness rules)
__device__ uint4 scratch_ps_v[(size_t)ND * TS * DIM / 8];   // 16 MB

// fp32 -> f16 convert, 8 front-batched LDG.128 per thread (MLP=8)
__global__ void cvt_ps_kernel(const float4* __restrict__ src) {
    int i = blockIdx.x * blockDim.x + threadIdx.x;    // 262144 threads
    float4 v[8];
    #pragma unroll
    for (int j = 0; j < 8; j++) v[j] = src[8 * (size_t)i + j];   // batched loads
    #pragma unroll
    for (int j = 0; j < 4; j++) {
        uint4 o; __half2 h;
        h = __floats2half2_rn(v[2*j].x,   v[2*j].y);   o.x = *reinterpret_cast<uint32_t*>(&h);
        h = __floats2half2_rn(v[2*j].z,   v[2*j].w);   o.y = *reinterpret_cast<uint32_t*>(&h);
        h = __floats2half2_rn(v[2*j+1].x, v[2*j+1].y); o.z = *reinterpret_cast<uint32_t*>(&h);
        h = __floats2half2_rn(v[2*j+1].z, v[2*j+1].w); o.w = *reinterpret_cast<uint32_t*>(&h);
        scratch_ps_v[4 * (size_t)i + j] = o;
    }
}

__device__ __forceinline__ uint32_t smem_u32(const void* p) {
    uint32_t a;
    asm("{ .reg .u64 t; cvta.to.shared.u64 t, %1; cvt.u32.u64 %0, t; }" : "=r"(a) : "l"(p));
    return a;
}
__device__ __forceinline__ unsigned pack_h2(float lo, float hi) {
    __half2 h = __floats2half2_rn(lo, hi);
    return *reinterpret_cast<unsigned*>(&h);
}
__device__ __forceinline__ void mma_f16(float c[4],
                                        unsigned a0, unsigned a1, unsigned a2, unsigned a3,
                                        unsigned b0, unsigned b1) {
    asm volatile(
        "mma.sync.aligned.m16n8k16.row.col.f32.f16.f16.f32 "
        "{%0,%1,%2,%3}, {%4,%5,%6,%7}, {%8,%9}, {%0,%1,%2,%3};\n"
        : "+f"(c[0]), "+f"(c[1]), "+f"(c[2]), "+f"(c[3])
        : "r"(a0), "r"(a1), "r"(a2), "r"(a3), "r"(b0), "r"(b1));
}
#define LDM_X4(reg, addr)                                                          \
    asm volatile("ldmatrix.sync.aligned.m8n8.x4.shared.b16 {%0,%1,%2,%3}, [%4];\n" \
                 : "=r"((reg)[0]), "=r"((reg)[1]), "=r"((reg)[2]), "=r"((reg)[3])  \
                 : "r"(addr))

__global__ __launch_bounds__(THREADS, 4)
void colbert_kernel(const float* __restrict__ qs, float* __restrict__ out) {
    __shared__ __align__(1024) char Bs[2 * BUFB];

    const int tid   = threadIdx.x;
    const int w     = tid >> 5;          // warp = query within group
    const int lane  = tid & 31;
    const int g     = lane >> 2;
    const int t     = lane & 3;
    const int c_doc = blockIdx.x;
    const int qg    = blockIdx.y;
    const uint32_t sb = smem_u32(Bs);

    const uint4* gsrc = scratch_ps_v + (size_t)c_doc * TS * (DIM / 8);

    // ---- prologue: async-copy chunk 0 into buffer 0 (XOR-swizzled rows) ----
    #pragma unroll
    for (int j = 0; j < 8; j++) {
        int f = j * THREADS + tid;       // 16B unit index, 1024 per chunk
        int r = f >> 4;                  // token row (16 units per 256B row)
        int c = f & 15;
        uint32_t dst = sb + r * ROWB + ((c ^ (r & 7)) << 4);
        asm volatile("cp.async.cg.shared.global [%0], [%1], 16;\n" :: "r"(dst), "l"(gsrc + f));
    }
    asm volatile("cp.async.commit_group;\n");

    // ---- A fragments: this warp's query (32 rows x 128 dims), fp32 -> f16 ----
    unsigned Af[2][8][4];
    {
        const int rbase = (qg * G_Q + w) * TQ;
        #pragma unroll
        for (int mt = 0; mt < 2; mt++) {
            #pragma unroll
            for (int ks = 0; ks < 8; ks++) {
                const int r0 = rbase + mt * 16 + g;
                const int cc = ks * 16 + t * 2;
                const float2* p0 = reinterpret_cast<const float2*>(qs + (size_t)r0 * DIM + cc);
                const float2* p1 = reinterpret_cast<const float2*>(qs + (size_t)(r0 + 8) * DIM + cc);
                float2 v00 = p0[0];
                float2 v02 = p0[4];
                float2 v10 = p1[0];
                float2 v12 = p1[4];
                Af[mt][ks][0] = pack_h2(v00.x, v00.y);
                Af[mt][ks][1] = pack_h2(v10.x, v10.y);
                Af[mt][ks][2] = pack_h2(v02.x, v02.y);
                Af[mt][ks][3] = pack_h2(v12.x, v12.y);
            }
        }
    }

    float rmax0 = -1e30f, rmax1 = -1e30f, rmax2 = -1e30f, rmax3 = -1e30f;

    const int rl = lane & 7;             // B: row provider within 8x8 matrix
    const int mc = lane >> 3;            // B: matrix select

    #pragma unroll 1
    for (int ch = 0; ch < NCHUNK; ch++) {
        asm volatile("cp.async.wait_group 0;\n");
        __syncthreads();

        if (ch + 1 < NCHUNK) {
            const uint4* gs2  = gsrc + (size_t)(ch + 1) * SN * (DIM / 8);
            uint32_t     dbuf = sb + ((ch + 1) & 1) * BUFB;
            #pragma unroll
            for (int j = 0; j < 8; j++) {
                int f = j * THREADS + tid;
                int r = f >> 4;
                int c = f & 15;
                uint32_t dst = dbuf + r * ROWB + ((c ^ (r & 7)) << 4);
                asm volatile("cp.async.cg.shared.global [%0], [%1], 16;\n" :: "r"(dst), "l"(gs2 + f));
            }
            asm volatile("cp.async.commit_group;\n");
        }

        // ---- compute on buffer ch&1, software-pipelined ldmatrix (1 ahead) ----
        const uint32_t cbase = sb + (ch & 1) * BUFB + rl * ROWB;
        uint32_t B[2][4];
        float cA[4], cB[4];
        LDM_X4(B[0], cbase + ((mc ^ rl) << 4));         // step 0: nf=0, kp=0
        #pragma unroll
        for (int p = 0; p < 32; p++) {                  // p = nf*4 + kp
            const int kp = p & 3;
            if (p + 1 < 32) {
                const int nf2 = (p + 1) >> 2;
                const int kp2 = (p + 1) & 3;
                LDM_X4(B[(p + 1) & 1],
                       cbase + nf2 * 8 * ROWB + ((((kp2 << 2) | mc) ^ rl) << 4));
            }
            const uint32_t* b = B[p & 1];
            if (kp == 0) {
                cA[0] = cA[1] = cA[2] = cA[3] = 0.f;
                cB[0] = cB[1] = cB[2] = cB[3] = 0.f;
            }
            mma_f16(cA, Af[0][2*kp][0],   Af[0][2*kp][1],   Af[0][2*kp][2],   Af[0][2*kp][3],   b[0], b[1]);
            mma_f16(cB, Af[1][2*kp][0],   Af[1][2*kp][1],   Af[1][2*kp][2],   Af[1][2*kp][3],   b[0], b[1]);
            mma_f16(cA, Af[0][2*kp+1][0], Af[0][2*kp+1][1], Af[0][2*kp+1][2], Af[0][2*kp+1][3], b[2], b[3]);
            mma_f16(cB, Af[1][2*kp+1][0], Af[1][2*kp+1][1], Af[1][2*kp+1][2], Af[1][2*kp+1][3], b[2], b[3]);
            if (kp == 3) {
                rmax0 = fmaxf(rmax0, fmaxf(cA[0], cA[1]));
                rmax1 = fmaxf(rmax1, fmaxf(cA[2], cA[3]));
                rmax2 = fmaxf(rmax2, fmaxf(cB[0], cB[1]));
                rmax3 = fmaxf(rmax3, fmaxf(cB[2], cB[3]));
            }
        }
    }

    // ---- reduce: complete row maxes across the 4 lanes sharing g ----
    #pragma unroll
    for (int off = 1; off <= 2; off <<= 1) {
        rmax0 = fmaxf(rmax0, __shfl_xor_sync(0xffffffffu, rmax0, off));
        rmax1 = fmaxf(rmax1, __shfl_xor_sync(0xffffffffu, rmax1, off));
        rmax2 = fmaxf(rmax2, __shfl_xor_sync(0xffffffffu, rmax2, off));
        rmax3 = fmaxf(rmax3, __shfl_xor_sync(0xffffffffu, rmax3, off));
    }
    float v = rmax0 + rmax1 + rmax2 + rmax3;   // rows {g, g+8, g+16, g+24}
    v += __shfl_xor_sync(0xffffffffu, v, 4);
    v += __shfl_xor_sync(0xffffffffu, v, 8);
    v += __shfl_xor_sync(0xffffffffu, v, 16);

    if (lane == 0) {
        out[(qg * G_Q + w) * ND + c_doc] = v;
    }
}

extern "C" void kernel_launch(void* const* d_in, const int* in_sizes, int n_in,
                              void* d_out, int out_size) {
    const float* qs = (const float*)d_in[0];   // 64*32*128
    const float* ps = (const float*)d_in[1];   // 64*1024*128
    float* out = (float*)d_out;                // 64*64

    cvt_ps_kernel<<<(ND * TS * DIM / 32) / 256, 256>>>((const float4*)ps);

    dim3 grid(ND, NQ / G_Q);                   // (64 docs, 16 query groups)
    colbert_kernel<<<grid, THREADS>>>(qs, out);
}

// round 16
// speedup vs baseline: 1.0206x; 1.0206x over previous
#include <cuda_runtime.h>
#include <cuda_fp16.h>
#include <cstdint>

// ColBERT MaxSim on GB300 (sm_103): R13 main + PDL-overlapped cvt.
// cvt (primary) converts ps fp32->f16 chunk-major and publishes per-(doc,chunk)
// flags; main (secondary, ProgrammaticStreamSerialization) launches early and
// spin-checks flags (free on graph replays; flags monotonic, data idempotent).
// qs: (64, 32, 128) fp32 ; ps: (64, 1024, 128) fp32 ; out: (64, 64) fp32

#define NQ       64
#define TQ       32
#define ND       64
#define TS       1024
#define DIM      128
#define G_Q      4                    // queries per CTA (1 per warp)
#define THREADS  128
#define SN       64                   // doc tokens per chunk
#define NCHUNK   (TS / SN)            // 16
#define ROWB     256                  // bytes per token row in smem (128 f16)
#define BUFB     (SN * ROWB)          // 16 KB per buffer

// fp16 ps scratch + publish flags (device-global; allocation-free)
__device__ uint4    scratch_ps_v[(size_t)ND * TS * DIM / 8];   // 16 MB
__device__ unsigned g_ready[ND * NCHUNK];                      // zero-init at load

// ---- primary: fp32->f16 convert, one block per (doc, chunk), chunk-major ----
__global__ void cvt_ps_kernel(const float4* __restrict__ src) {
    // allow the dependent (main) kernel to launch immediately
    asm volatile("griddepcontrol.launch_dependents;" ::: "memory");

    const int bid   = blockIdx.x;          // bid = chunk*64 + doc
    const int chunk = bid >> 6;
    const int doc   = bid & 63;
    const int tid   = threadIdx.x;         // 512 threads

    const size_t ib = ((size_t)doc * TS + (size_t)chunk * SN) * (DIM / 4);  // float4
    const size_t ob = ((size_t)doc * TS + (size_t)chunk * SN) * (DIM / 8);  // uint4

    float4 v[4];
    #pragma unroll
    for (int j = 0; j < 2; j++) {
        int idx = j * 512 + tid;
        v[2 * j]     = src[ib + 2 * idx];
        v[2 * j + 1] = src[ib + 2 * idx + 1];
    }
    #pragma unroll
    for (int j = 0; j < 2; j++) {
        int idx = j * 512 + tid;
        uint4 o; __half2 h;
        h = __floats2half2_rn(v[2*j].x,   v[2*j].y);   o.x = *reinterpret_cast<uint32_t*>(&h);
        h = __floats2half2_rn(v[2*j].z,   v[2*j].w);   o.y = *reinterpret_cast<uint32_t*>(&h);
        h = __floats2half2_rn(v[2*j+1].x, v[2*j+1].y); o.z = *reinterpret_cast<uint32_t*>(&h);
        h = __floats2half2_rn(v[2*j+1].z, v[2*j+1].w); o.w = *reinterpret_cast<uint32_t*>(&h);
        scratch_ps_v[ob + idx] = o;
    }
    __syncthreads();
    if (tid == 0) {
        asm volatile("st.release.gpu.global.u32 [%0], %1;"
                     :: "l"(g_ready + doc * NCHUNK + chunk), "r"(1u) : "memory");
    }
}

__device__ __forceinline__ void spin_flag(const unsigned* f) {
    unsigned v;
    do {
        asm volatile("ld.acquire.gpu.global.u32 %0, [%1];" : "=r"(v) : "l"(f));
    } while (v == 0u);
}
__device__ __forceinline__ uint32_t smem_u32(const void* p) {
    uint32_t a;
    asm("{ .reg .u64 t; cvta.to.shared.u64 t, %1; cvt.u32.u64 %0, t; }" : "=r"(a) : "l"(p));
    return a;
}
__device__ __forceinline__ unsigned pack_h2(float lo, float hi) {
    __half2 h = __floats2half2_rn(lo, hi);
    return *reinterpret_cast<unsigned*>(&h);
}
__device__ __forceinline__ void mma_f16(float c[4],
                                        unsigned a0, unsigned a1, unsigned a2, unsigned a3,
                                        unsigned b0, unsigned b1) {
    asm volatile(
        "mma.sync.aligned.m16n8k16.row.col.f32.f16.f16.f32 "
        "{%0,%1,%2,%3}, {%4,%5,%6,%7}, {%8,%9}, {%0,%1,%2,%3};\n"
        : "+f"(c[0]), "+f"(c[1]), "+f"(c[2]), "+f"(c[3])
        : "r"(a0), "r"(a1), "r"(a2), "r"(a3), "r"(b0), "r"(b1));
}
#define LDM_X4(reg, addr)                                                          \
    asm volatile("ldmatrix.sync.aligned.m8n8.x4.shared.b16 {%0,%1,%2,%3}, [%4];\n" \
                 : "=r"((reg)[0]), "=r"((reg)[1]), "=r"((reg)[2]), "=r"((reg)[3])  \
                 : "r"(addr))

__global__ __launch_bounds__(THREADS, 4)
void colbert_kernel(const float* __restrict__ qs, float* __restrict__ out) {
    __shared__ __align__(1024) char Bs[2 * BUFB];

    const int tid   = threadIdx.x;
    const int w     = tid >> 5;          // warp = query within group
    const int lane  = tid & 31;
    const int g     = lane >> 2;
    const int t     = lane & 3;
    const int c_doc = blockIdx.x;
    const int qg    = blockIdx.y;
    const uint32_t sb = smem_u32(Bs);
    const unsigned* myflags = g_ready + c_doc * NCHUNK;

    const uint4* gsrc = scratch_ps_v + (size_t)c_doc * TS * (DIM / 8);

    // ---- prologue: wait chunk 0 published, then async-copy into buffer 0 ----
    if (tid == 0) spin_flag(myflags + 0);
    __syncthreads();
    #pragma unroll
    for (int j = 0; j < 8; j++) {
        int f = j * THREADS + tid;       // 16B unit index, 1024 per chunk
        int r = f >> 4;                  // token row (16 units per 256B row)
        int c = f & 15;
        uint32_t dst = sb + r * ROWB + ((c ^ (r & 7)) << 4);
        asm volatile("cp.async.cg.shared.global [%0], [%1], 16;\n" :: "r"(dst), "l"(gsrc + f));
    }
    asm volatile("cp.async.commit_group;\n");

    // ---- A fragments: this warp's query (32 rows x 128 dims), fp32 -> f16 ----
    unsigned Af[2][8][4];
    {
        const int rbase = (qg * G_Q + w) * TQ;
        #pragma unroll
        for (int mt = 0; mt < 2; mt++) {
            #pragma unroll
            for (int ks = 0; ks < 8; ks++) {
                const int r0 = rbase + mt * 16 + g;
                const int cc = ks * 16 + t * 2;
                const float2* p0 = reinterpret_cast<const float2*>(qs + (size_t)r0 * DIM + cc);
                const float2* p1 = reinterpret_cast<const float2*>(qs + (size_t)(r0 + 8) * DIM + cc);
                float2 v00 = p0[0];
                float2 v02 = p0[4];
                float2 v10 = p1[0];
                float2 v12 = p1[4];
                Af[mt][ks][0] = pack_h2(v00.x, v00.y);
                Af[mt][ks][1] = pack_h2(v10.x, v10.y);
                Af[mt][ks][2] = pack_h2(v02.x, v02.y);
                Af[mt][ks][3] = pack_h2(v12.x, v12.y);
            }
        }
    }

    float rmax0 = -1e30f, rmax1 = -1e30f, rmax2 = -1e30f, rmax3 = -1e30f;

    const int rl = lane & 7;             // B: row provider within 8x8 matrix
    const int mc = lane >> 3;            // B: matrix select

    #pragma unroll 1
    for (int ch = 0; ch < NCHUNK; ch++) {
        // tid0 checks next chunk's flag while this chunk's copies drain
        if (ch + 1 < NCHUNK && tid == 0) spin_flag(myflags + ch + 1);
        asm volatile("cp.async.wait_group 0;\n");
        __syncthreads();                 // publishes tid0's flag result to all

        if (ch + 1 < NCHUNK) {
            const uint4* gs2  = gsrc + (size_t)(ch + 1) * SN * (DIM / 8);
            uint32_t     dbuf = sb + ((ch + 1) & 1) * BUFB;
            #pragma unroll
            for (int j = 0; j < 8; j++) {
                int f = j * THREADS + tid;
                int r = f >> 4;
                int c = f & 15;
                uint32_t dst = dbuf + r * ROWB + ((c ^ (r & 7)) << 4);
                asm volatile("cp.async.cg.shared.global [%0], [%1], 16;\n" :: "r"(dst), "l"(gs2 + f));
            }
            asm volatile("cp.async.commit_group;\n");
        }

        // ---- compute on buffer ch&1, software-pipelined ldmatrix (1 ahead) ----
        const uint32_t cbase = sb + (ch & 1) * BUFB + rl * ROWB;
        uint32_t B[2][4];
        float cA[4], cB[4];
        LDM_X4(B[0], cbase + ((mc ^ rl) << 4));         // step 0: nf=0, kp=0
        #pragma unroll
        for (int p = 0; p < 32; p++) {                  // p = nf*4 + kp
            const int kp = p & 3;
            if (p + 1 < 32) {
                const int nf2 = (p + 1) >> 2;
                const int kp2 = (p + 1) & 3;
                LDM_X4(B[(p + 1) & 1],
                       cbase + nf2 * 8 * ROWB + ((((kp2 << 2) | mc) ^ rl) << 4));
            }
            const uint32_t* b = B[p & 1];
            if (kp == 0) {
                cA[0] = cA[1] = cA[2] = cA[3] = 0.f;
                cB[0] = cB[1] = cB[2] = cB[3] = 0.f;
            }
            mma_f16(cA, Af[0][2*kp][0],   Af[0][2*kp][1],   Af[0][2*kp][2],   Af[0][2*kp][3],   b[0], b[1]);
            mma_f16(cB, Af[1][2*kp][0],   Af[1][2*kp][1],   Af[1][2*kp][2],   Af[1][2*kp][3],   b[0], b[1]);
            mma_f16(cA, Af[0][2*kp+1][0], Af[0][2*kp+1][1], Af[0][2*kp+1][2], Af[0][2*kp+1][3], b[2], b[3]);
            mma_f16(cB, Af[1][2*kp+1][0], Af[1][2*kp+1][1], Af[1][2*kp+1][2], Af[1][2*kp+1][3], b[2], b[3]);
            if (kp == 3) {
                rmax0 = fmaxf(rmax0, fmaxf(cA[0], cA[1]));
                rmax1 = fmaxf(rmax1, fmaxf(cA[2], cA[3]));
                rmax2 = fmaxf(rmax2, fmaxf(cB[0], cB[1]));
                rmax3 = fmaxf(rmax3, fmaxf(cB[2], cB[3]));
            }
        }
    }

    // ---- reduce: complete row maxes across the 4 lanes sharing g ----
    #pragma unroll
    for (int off = 1; off <= 2; off <<= 1) {
        rmax0 = fmaxf(rmax0, __shfl_xor_sync(0xffffffffu, rmax0, off));
        rmax1 = fmaxf(rmax1, __shfl_xor_sync(0xffffffffu, rmax1, off));
        rmax2 = fmaxf(rmax2, __shfl_xor_sync(0xffffffffu, rmax2, off));
        rmax3 = fmaxf(rmax3, __shfl_xor_sync(0xffffffffu, rmax3, off));
    }
    float v = rmax0 + rmax1 + rmax2 + rmax3;   // rows {g, g+8, g+16, g+24}
    v += __shfl_xor_sync(0xffffffffu, v, 4);
    v += __shfl_xor_sync(0xffffffffu, v, 8);
    v += __shfl_xor_sync(0xffffffffu, v, 16);

    if (lane == 0) {
        out[(qg * G_Q + w) * ND + c_doc] = v;
    }
}

extern "C" void kernel_launch(void* const* d_in, const int* in_sizes, int n_in,
                              void* d_out, int out_size) {
    const float* qs = (const float*)d_in[0];   // 64*32*128
    const float* ps = (const float*)d_in[1];   // 64*1024*128
    float* out = (float*)d_out;                // 64*64

    // primary: chunk-major convert (1024 blocks = 16 chunks x 64 docs)
    cvt_ps_kernel<<<ND * NCHUNK, 512>>>((const float4*)ps);

    // secondary: main kernel with programmatic dependent launch (overlaps cvt)
    cudaLaunchConfig_t cfg = {};
    cfg.gridDim  = dim3(ND, NQ / G_Q, 1);
    cfg.blockDim = dim3(THREADS, 1, 1);
    cfg.dynamicSmemBytes = 0;
    cudaLaunchAttribute at[1];
    at[0].id = cudaLaunchAttributeProgrammaticStreamSerialization;
    at[0].val.programmaticStreamSerializationAllowed = 1;
    cfg.attrs = at;
    cfg.numAttrs = 1;
    cudaLaunchKernelEx(&cfg, colbert_kernel, qs, out);
}